// round 8
// baseline (speedup 1.0000x reference)
#include <cuda_runtime.h>
#include <math_constants.h>

// ---------------------------------------------------------------------------
// Problem constants
// ---------------------------------------------------------------------------
#define BATCH 4
#define NPTS  1024
#define CIN   768
#define KNN   20
#define HDIM  1152    // 512 + 256 + 128 + 256
#define PCH   32      // pooling chunks
#define EPS   1e-5f

// ---------------------------------------------------------------------------
// Scratch (device globals; no allocation allowed)
// ---------------------------------------------------------------------------
__device__ float g_XT [BATCH * NPTS * CIN];     // x transposed: (B, N, C)
__device__ float g_G  [BATCH * NPTS * NPTS];    // gram matrix
__device__ float g_diag[BATCH * NPTS];          // gram diagonal
__device__ int   g_idx[BATCH * NPTS * KNN];     // knn indices
__device__ float g_U  [BATCH * NPTS * 512];     // W_left  @ x
__device__ float g_V  [BATCH * NPTS * 512];     // W_right @ x
__device__ float g_H  [BATCH * NPTS * HDIM];    // concat(x1,x2,x3,x4)
__device__ float g_H5 [BATCH * NPTS * 1024];    // conv5 output
__device__ float g_pmax[BATCH * PCH * 1024];
__device__ float g_psum[BATCH * PCH * 1024];
__device__ float g_pool[BATCH * 2048];
__device__ float g_z   [BATCH * 512];

// ---------------------------------------------------------------------------
// Packed f32x2 helpers (each lane independently rn-rounded -> bit-identical
// per output to scalar FFMA).
// ---------------------------------------------------------------------------
static __device__ __forceinline__ void upk2(unsigned long long v, float& x, float& y) {
    asm("mov.b64 {%0, %1}, %2;" : "=f"(x), "=f"(y) : "l"(v));
}
static __device__ __forceinline__ void ffma2(unsigned long long& d,
                                             unsigned long long a,
                                             unsigned long long b) {
    asm("fma.rn.f32x2 %0, %1, %2, %0;" : "+l"(d) : "l"(a), "l"(b));
}

// ---------------------------------------------------------------------------
// Transpose: x (B, C, N) -> XT (B, N, C)
// ---------------------------------------------------------------------------
__global__ void transpose_kernel(const float* __restrict__ x, float* __restrict__ xt) {
    __shared__ float tile[32][33];
    int b  = blockIdx.z;
    int c0 = blockIdx.y * 32;
    int n0 = blockIdx.x * 32;
    const float* xb  = x  + (long)b * CIN * NPTS;
    float*       xtb = xt + (long)b * NPTS * CIN;
    int tx = threadIdx.x, ty = threadIdx.y;            // 32 x 8
#pragma unroll
    for (int i = 0; i < 32; i += 8)
        tile[ty + i][tx] = xb[(long)(c0 + ty + i) * NPTS + n0 + tx];
    __syncthreads();
#pragma unroll
    for (int i = 0; i < 32; i += 8)
        xtb[(long)(n0 + ty + i) * CIN + c0 + tx] = tile[tx][ty + i];
}

// ---------------------------------------------------------------------------
// Tiled SGEMM with dual-source N split (B1 for n0<N1, else B2).
// 128x128 tiles, 8x8 per-thread outputs via packed fma.rn.f32x2.
// B stored DUPLICATED in smem ({b,b} pairs) so the inner loop has zero MOVs:
// per k-step = 2 LDS.128 (A row-pairs) + 4 LDS.128 (B dup pairs) + 32 FFMA2.
// Sequential k accumulation -> bit-identical to scalar FFMA chain.
// sym != 0: only blocks bx <= by computed (Gram symmetry; mirrored later).
// Requirements: M % 128 == 0, N % 128 == 0, K % 16 == 0
// ---------------------------------------------------------------------------
#define BM 128
#define BN 128
#define BK 16

__global__ void __launch_bounds__(256, 2)
gemm_nt(const float* __restrict__ A, int lda, long strideA,
        const float* __restrict__ B1, const float* __restrict__ B2,
        int ldb, long strideB,
        float* __restrict__ C1, float* __restrict__ C2,
        int ldc, long strideC,
        int N1, int K,
        const float* __restrict__ bn, int bnN, int sym)
{
    if (sym && (int)blockIdx.x > (int)blockIdx.y) return;

    __shared__ __align__(16) float As [2][BK][BM];       // 16 KB
    __shared__ __align__(16) float Bs2[2][BK][BN * 2];   // 32 KB (dup pairs)

    const int bz = blockIdx.z;
    const int m0 = blockIdx.y * BM;
    const int nb0 = blockIdx.x * BN;

    const float* Bsel;
    float*       Csel;
    int n0;
    if (nb0 < N1) { Bsel = B1; Csel = C1; n0 = nb0; }
    else          { Bsel = B2; Csel = C2; n0 = nb0 - N1; }

    const float* Ab = A    + (long)bz * strideA;
    const float* Bb = Bsel + (long)bz * strideB;
    float*       Cb = Csel + (long)bz * strideC;

    const int tid = threadIdx.x;
    const int lr = tid >> 2;            // 0..63
    const int lc = (tid & 3) * 4;       // 0,4,8,12
    const int ty = tid >> 4;            // 0..15
    const int tx = tid & 15;            // 0..15

    unsigned long long acc[4][8];       // row-pairs (2rp,2rp+1) x 8 cols
#pragma unroll
    for (int i = 0; i < 4; i++)
#pragma unroll
        for (int j = 0; j < 8; j++) acc[i][j] = 0ull;

    const int nTiles = K / BK;
    float4 pa0, pa1, pb0, pb1;

    // prefetch tile 0
    pa0 = *reinterpret_cast<const float4*>(&Ab[(long)(m0 + lr)      * lda + lc]);
    pa1 = *reinterpret_cast<const float4*>(&Ab[(long)(m0 + lr + 64) * lda + lc]);
    pb0 = *reinterpret_cast<const float4*>(&Bb[(long)(n0 + lr)      * ldb + lc]);
    pb1 = *reinterpret_cast<const float4*>(&Bb[(long)(n0 + lr + 64) * ldb + lc]);
    {
        As[0][lc + 0][lr] = pa0.x; As[0][lc + 1][lr] = pa0.y;
        As[0][lc + 2][lr] = pa0.z; As[0][lc + 3][lr] = pa0.w;
        As[0][lc + 0][lr + 64] = pa1.x; As[0][lc + 1][lr + 64] = pa1.y;
        As[0][lc + 2][lr + 64] = pa1.z; As[0][lc + 3][lr + 64] = pa1.w;
        float pv[4] = {pb0.x, pb0.y, pb0.z, pb0.w};
        float qv[4] = {pb1.x, pb1.y, pb1.z, pb1.w};
#pragma unroll
        for (int i = 0; i < 4; i++) {
            Bs2[0][lc + i][2 * lr + 0]        = pv[i];
            Bs2[0][lc + i][2 * lr + 1]        = pv[i];
            Bs2[0][lc + i][2 * (lr + 64) + 0] = qv[i];
            Bs2[0][lc + i][2 * (lr + 64) + 1] = qv[i];
        }
    }
    __syncthreads();

    for (int t = 0; t < nTiles; t++) {
        const int cur = t & 1;
        if (t + 1 < nTiles) {
            const int k0 = (t + 1) * BK;
            pa0 = *reinterpret_cast<const float4*>(&Ab[(long)(m0 + lr)      * lda + k0 + lc]);
            pa1 = *reinterpret_cast<const float4*>(&Ab[(long)(m0 + lr + 64) * lda + k0 + lc]);
            pb0 = *reinterpret_cast<const float4*>(&Bb[(long)(n0 + lr)      * ldb + k0 + lc]);
            pb1 = *reinterpret_cast<const float4*>(&Bb[(long)(n0 + lr + 64) * ldb + k0 + lc]);
        }

#pragma unroll
        for (int k = 0; k < BK; k++) {
            ulonglong2 ap01 = *reinterpret_cast<const ulonglong2*>(&As[cur][k][ty * 8]);
            ulonglong2 ap23 = *reinterpret_cast<const ulonglong2*>(&As[cur][k][ty * 8 + 4]);
            unsigned long long ap[4] = {ap01.x, ap01.y, ap23.x, ap23.y};
#pragma unroll
            for (int jj = 0; jj < 4; jj++) {
                ulonglong2 bb = *reinterpret_cast<const ulonglong2*>(
                    &Bs2[cur][k][(tx * 8 + jj * 2) * 2]);
#pragma unroll
                for (int rp = 0; rp < 4; rp++) {
                    ffma2(acc[rp][2 * jj + 0], ap[rp], bb.x);
                    ffma2(acc[rp][2 * jj + 1], ap[rp], bb.y);
                }
            }
        }

        if (t + 1 < nTiles) {
            const int nxt = 1 - cur;
            As[nxt][lc + 0][lr] = pa0.x; As[nxt][lc + 1][lr] = pa0.y;
            As[nxt][lc + 2][lr] = pa0.z; As[nxt][lc + 3][lr] = pa0.w;
            As[nxt][lc + 0][lr + 64] = pa1.x; As[nxt][lc + 1][lr + 64] = pa1.y;
            As[nxt][lc + 2][lr + 64] = pa1.z; As[nxt][lc + 3][lr + 64] = pa1.w;
            float pv[4] = {pb0.x, pb0.y, pb0.z, pb0.w};
            float qv[4] = {pb1.x, pb1.y, pb1.z, pb1.w};
#pragma unroll
            for (int i = 0; i < 4; i++) {
                Bs2[nxt][lc + i][2 * lr + 0]        = pv[i];
                Bs2[nxt][lc + i][2 * lr + 1]        = pv[i];
                Bs2[nxt][lc + i][2 * (lr + 64) + 0] = qv[i];
                Bs2[nxt][lc + i][2 * (lr + 64) + 1] = qv[i];
            }
        }
        __syncthreads();
    }

    // epilogue
    const int cm = m0 + ty * 8;
    const int cn = n0 + tx * 8;
    float sc[8], sh[8];
    if (bn) {
#pragma unroll
        for (int j = 0; j < 8; j++) {
            int n = cn + j;
            float g = bn[n], b = bn[bnN + n], m = bn[2 * bnN + n], v = bn[3 * bnN + n];
            sc[j] = g * rsqrtf(v + EPS);
            sh[j] = b - m * sc[j];
        }
    }
#pragma unroll
    for (int rp = 0; rp < 4; rp++) {
        float lo[8], hi[8];
#pragma unroll
        for (int j = 0; j < 8; j++) upk2(acc[rp][j], lo[j], hi[j]);
        if (bn) {
#pragma unroll
            for (int j = 0; j < 8; j++) {
                float v0 = lo[j] * sc[j] + sh[j];
                float v1 = hi[j] * sc[j] + sh[j];
                lo[j] = v0 > 0.f ? v0 : 0.2f * v0;
                hi[j] = v1 > 0.f ? v1 : 0.2f * v1;
            }
        }
        long r0 = (long)(cm + rp * 2) * ldc + cn;
        long r1 = r0 + ldc;
        *reinterpret_cast<float4*>(&Cb[r0])     = make_float4(lo[0], lo[1], lo[2], lo[3]);
        *reinterpret_cast<float4*>(&Cb[r0 + 4]) = make_float4(lo[4], lo[5], lo[6], lo[7]);
        *reinterpret_cast<float4*>(&Cb[r1])     = make_float4(hi[0], hi[1], hi[2], hi[3]);
        *reinterpret_cast<float4*>(&Cb[r1 + 4]) = make_float4(hi[4], hi[5], hi[6], hi[7]);
    }
}

// ---------------------------------------------------------------------------
// Gram mirror: fill G[n][m] (m >= 128*((n>>7)+1)) from G[m][n].
// Bit-identical because FMA(a,b,c) == FMA(b,a,c) with same k order.
// ---------------------------------------------------------------------------
__global__ void mirror_kernel(float* __restrict__ G)
{
    int b  = blockIdx.z;
    int m0 = blockIdx.x * 32;   // destination cols
    int n0 = blockIdx.y * 32;   // destination rows
    if (m0 < 128 * ((n0 >> 7) + 1)) return;   // tile already computed

    __shared__ float tile[32][33];
    float* Gb = G + (long)b * NPTS * NPTS;
    int tx = threadIdx.x, ty = threadIdx.y;    // 32 x 8
#pragma unroll
    for (int i = 0; i < 32; i += 8)
        tile[ty + i][tx] = Gb[(long)(m0 + ty + i) * NPTS + n0 + tx];
    __syncthreads();
#pragma unroll
    for (int i = 0; i < 32; i += 8)
        Gb[(long)(n0 + ty + i) * NPTS + m0 + tx] = tile[tx][ty + i];
}

// ---------------------------------------------------------------------------
// Extract Gram diagonal
// ---------------------------------------------------------------------------
__global__ void diag_kernel(const float* __restrict__ G, float* __restrict__ diag)
{
    int t = blockIdx.x * 256 + threadIdx.x;     // over BATCH*NPTS
    int b = t >> 10, m = t & 1023;
    diag[t] = G[((long)b * NPTS + m) * NPTS + m];
}

// ---------------------------------------------------------------------------
// Top-K (K=20): register-resident two-phase selection.
// key[m] = 2*G[n][m] - G[m][m]; descending value, tie -> lower index.
// ---------------------------------------------------------------------------
__global__ void __launch_bounds__(256)
topk_kernel(const float* __restrict__ G, const float* __restrict__ diag,
            int* __restrict__ idx)
{
    const int b = blockIdx.y;
    const int n = blockIdx.x;
    const float* Gb = G + ((long)b * NPTS + n) * NPTS;
    const float* db = diag + b * NPTS;

    const int tid  = threadIdx.x;
    const int lane = tid & 31;
    const int w    = tid >> 5;          // 0..7
    const int base = w * 128;

    float key[4];
#pragma unroll
    for (int q = 0; q < 4; q++) {
        int m = base + lane + 32 * q;
        key[q] = 2.f * Gb[m] - db[m];
    }

    __shared__ float wv[8][KNN];
    __shared__ int   wi[8][KNN];

    // Phase 1: per-warp top-20 (sorted desc, ties by ascending index)
    for (int it = 0; it < KNN; ++it) {
        float bv = key[0];
        int   bi = base + lane;
#pragma unroll
        for (int q = 1; q < 4; q++) {
            if (key[q] > bv) { bv = key[q]; bi = base + lane + 32 * q; }
        }
#pragma unroll
        for (int off = 16; off > 0; off >>= 1) {
            float ov = __shfl_xor_sync(0xffffffffu, bv, off);
            int   oi = __shfl_xor_sync(0xffffffffu, bi, off);
            if (ov > bv || (ov == bv && oi < bi)) { bv = ov; bi = oi; }
        }
        if (lane == 0) { wv[w][it] = bv; wi[w][it] = bi; }
        const int rel   = bi - base;
        const int l_win = rel & 31;
        const int q_win = rel >> 5;
        if (lane == l_win) {
#pragma unroll
            for (int q = 0; q < 4; q++)
                if (q == q_win) key[q] = -CUDART_INF_F;
        }
    }
    __syncthreads();

    // Phase 2: warp 0 merges 8 sorted lists of 20
    if (w == 0) {
        int ptr = 0;
        int* orow = idx + ((long)b * NPTS + n) * KNN;
        for (int it = 0; it < KNN; ++it) {
            float v = (lane < 8) ? wv[lane][ptr] : -CUDART_INF_F;
            int   i = (lane < 8) ? wi[lane][ptr] : 0x7fffffff;
            int   j = lane;
#pragma unroll
            for (int off = 4; off > 0; off >>= 1) {
                float ov = __shfl_xor_sync(0xffffffffu, v, off);
                int   oi = __shfl_xor_sync(0xffffffffu, i, off);
                int   oj = __shfl_xor_sync(0xffffffffu, j, off);
                if (ov > v || (ov == v && oi < i)) { v = ov; i = oi; j = oj; }
            }
            if (lane == 0) orow[it] = i;
            if (lane < 8 && lane == j) ptr++;
        }
    }
}

// ---------------------------------------------------------------------------
// EdgeConv aggregation (float4 across channels):
// out[n][o] = bn_lrelu( max_k U[idx[n,k]][o]  -  U[n][o] + V[n][o] )
// ---------------------------------------------------------------------------
__global__ void __launch_bounds__(256)
aggregate_kernel(const float* __restrict__ U, const float* __restrict__ V,
                 const int* __restrict__ idx, const float* __restrict__ bn,
                 float* __restrict__ out, int O, int ldo)
{
    int b = blockIdx.y, n = blockIdx.x;
    __shared__ int nb[KNN];
    int tid = threadIdx.x;
    if (tid < KNN) nb[tid] = idx[((long)b * NPTS + n) * KNN + tid];
    __syncthreads();

    const float* Ub = U + (long)b * NPTS * O;
    const float* un = Ub + (long)n * O;
    const float* vn = V + ((long)b * NPTS + n) * O;
    float*       on = out + ((long)b * NPTS + n) * ldo;

    const int O4 = O >> 2;
    for (int o4 = tid; o4 < O4; o4 += 256) {
        float4 mx = make_float4(-CUDART_INF_F, -CUDART_INF_F, -CUDART_INF_F, -CUDART_INF_F);
#pragma unroll
        for (int k = 0; k < KNN; k++) {
            float4 u = *reinterpret_cast<const float4*>(&Ub[(long)nb[k] * O + o4 * 4]);
            mx.x = fmaxf(mx.x, u.x); mx.y = fmaxf(mx.y, u.y);
            mx.z = fmaxf(mx.z, u.z); mx.w = fmaxf(mx.w, u.w);
        }
        float4 uo = *reinterpret_cast<const float4*>(&un[o4 * 4]);
        float4 vo = *reinterpret_cast<const float4*>(&vn[o4 * 4]);
        float4 gg = *reinterpret_cast<const float4*>(&bn[o4 * 4]);
        float4 be = *reinterpret_cast<const float4*>(&bn[O + o4 * 4]);
        float4 mm = *reinterpret_cast<const float4*>(&bn[2 * O + o4 * 4]);
        float4 vv = *reinterpret_cast<const float4*>(&bn[3 * O + o4 * 4]);
        float y0 = mx.x - uo.x + vo.x, y1 = mx.y - uo.y + vo.y;
        float y2 = mx.z - uo.z + vo.z, y3 = mx.w - uo.w + vo.w;
        float s0 = gg.x * rsqrtf(vv.x + EPS), s1 = gg.y * rsqrtf(vv.y + EPS);
        float s2 = gg.z * rsqrtf(vv.z + EPS), s3 = gg.w * rsqrtf(vv.w + EPS);
        y0 = (y0 - mm.x) * s0 + be.x; y1 = (y1 - mm.y) * s1 + be.y;
        y2 = (y2 - mm.z) * s2 + be.z; y3 = (y3 - mm.w) * s3 + be.w;
        float4 r;
        r.x = y0 > 0.f ? y0 : 0.2f * y0;
        r.y = y1 > 0.f ? y1 : 0.2f * y1;
        r.z = y2 > 0.f ? y2 : 0.2f * y2;
        r.w = y3 > 0.f ? y3 : 0.2f * y3;
        *reinterpret_cast<float4*>(&on[o4 * 4]) = r;
    }
}

// ---------------------------------------------------------------------------
// Pooling (max + mean over N), two-stage
// ---------------------------------------------------------------------------
__global__ void __launch_bounds__(256)
pool1_kernel(const float* __restrict__ H5, float* __restrict__ pmax, float* __restrict__ psum)
{
    int b = blockIdx.y, chunk = blockIdx.x;      // PCH chunks of 32 rows
    int tid = threadIdx.x;
    float mx[4] = {-CUDART_INF_F, -CUDART_INF_F, -CUDART_INF_F, -CUDART_INF_F};
    float sm[4] = {0.f, 0.f, 0.f, 0.f};
    const float* h = H5 + ((long)b * NPTS + chunk * 32) * 1024;
    for (int n = 0; n < 32; n++) {
        const float* row = h + (long)n * 1024;
#pragma unroll
        for (int q = 0; q < 4; q++) {
            float v = row[tid + 256 * q];
            mx[q] = fmaxf(mx[q], v);
            sm[q] += v;
        }
    }
#pragma unroll
    for (int q = 0; q < 4; q++) {
        int o = tid + 256 * q;
        pmax[((long)b * PCH + chunk) * 1024 + o] = mx[q];
        psum[((long)b * PCH + chunk) * 1024 + o] = sm[q];
    }
}

__global__ void __launch_bounds__(256)
pool2_kernel(const float* __restrict__ pmax, const float* __restrict__ psum,
             float* __restrict__ pooled)
{
    int b = blockIdx.y;
    int o = blockIdx.x * 256 + threadIdx.x;      // 0..1023
    float mx = -CUDART_INF_F, sm = 0.f;
    for (int c = 0; c < PCH; c++) {
        mx = fmaxf(mx, pmax[((long)b * PCH + c) * 1024 + o]);
        sm += psum[((long)b * PCH + c) * 1024 + o];
    }
    pooled[b * 2048 + o]        = mx;
    pooled[b * 2048 + 1024 + o] = sm * (1.f / NPTS);
}

// ---------------------------------------------------------------------------
// Head:  z = bn_lrelu(pooled @ Wl1^T);  out = z @ Wl3^T + bl3
// ---------------------------------------------------------------------------
__global__ void __launch_bounds__(256)
head1_kernel(const float* __restrict__ pooled, const float* __restrict__ Wl1,
             const float* __restrict__ bn6, float* __restrict__ z)
{
    int b = blockIdx.y, j = blockIdx.x;          // j < 512
    int tid = threadIdx.x;
    const float* p = pooled + b * 2048;
    const float* w = Wl1 + (long)j * 2048;
    float s = 0.f;
    for (int c = tid; c < 2048; c += 256) s += p[c] * w[c];
    __shared__ float red[256];
    red[tid] = s; __syncthreads();
    for (int st = 128; st > 0; st >>= 1) {
        if (tid < st) red[tid] += red[tid + st];
        __syncthreads();
    }
    if (tid == 0) {
        float y = red[0];
        float g = bn6[j], be = bn6[512 + j], mm = bn6[1024 + j], vv = bn6[1536 + j];
        y = (y - mm) * (g * rsqrtf(vv + EPS)) + be;
        z[b * 512 + j] = y > 0.f ? y : 0.2f * y;
    }
}

__global__ void __launch_bounds__(128)
head2_kernel(const float* __restrict__ z, const float* __restrict__ Wl3,
             const float* __restrict__ bl3, float* __restrict__ out)
{
    int b = blockIdx.y, t = blockIdx.x;          // t < 40
    int tid = threadIdx.x;
    const float* zb = z + b * 512;
    const float* w  = Wl3 + (long)t * 512;
    float s = 0.f;
    for (int c = tid; c < 512; c += 128) s += zb[c] * w[c];
    __shared__ float red[128];
    red[tid] = s; __syncthreads();
    for (int st = 64; st > 0; st >>= 1) {
        if (tid < st) red[tid] += red[tid + st];
        __syncthreads();
    }
    if (tid == 0) out[b * 40 + t] = red[0] + bl3[t];
}

// ---------------------------------------------------------------------------
// Host driver
// ---------------------------------------------------------------------------
static void launch_gemm2(const float* A, int lda, long sA,
                         const float* B1, const float* B2, int ldb, long sB,
                         float* C1, float* C2, int ldc, long sC,
                         int M, int N1, int N2, int K,
                         const float* bn, int bnN, int sym)
{
    dim3 grid((N1 + N2) / BN, M / BM, BATCH);
    gemm_nt<<<grid, 256>>>(A, lda, sA, B1, B2, ldb, sB, C1, C2, ldc, sC, N1, K, bn, bnN, sym);
}

static void run_edgeconv(const float* Xin, int lda, int Kdim,
                         const float* W, const float* bn, int O,
                         float* Hout, int ldo,
                         float* G, float* diag, int* idx, float* U, float* V)
{
    // 1) Gram matrix (lower-triangular blocks), mirror
    launch_gemm2(Xin, lda, (long)NPTS * lda, Xin, Xin, lda, (long)NPTS * lda,
                 G, G, NPTS, (long)NPTS * NPTS, NPTS, NPTS, 0, Kdim, nullptr, 0, 1);
    mirror_kernel<<<dim3(NPTS / 32, NPTS / 32, BATCH), dim3(32, 8)>>>(G);
    // 2) fused U/V gemm (placed here so it is the 4th launch overall -> profiled)
    launch_gemm2(Xin, lda, (long)NPTS * lda, W, W + Kdim, 2 * Kdim, 0,
                 U, V, O, (long)NPTS * O, NPTS, O, O, Kdim, nullptr, 0, 0);
    // 3) diag + top-20 per row
    diag_kernel<<<(BATCH * NPTS) / 256, 256>>>(G, diag);
    topk_kernel<<<dim3(NPTS, BATCH), 256>>>(G, diag, idx);
    // 4) gather + max + bn + lrelu
    aggregate_kernel<<<dim3(NPTS, BATCH), 256>>>(U, V, idx, bn, Hout, O, ldo);
}

extern "C" void kernel_launch(void* const* d_in, const int* in_sizes, int n_in,
                              void* d_out, int out_size)
{
    (void)in_sizes; (void)n_in; (void)out_size;
    const float* x   = (const float*)d_in[0];
    const float* W1  = (const float*)d_in[1];
    const float* bn1 = (const float*)d_in[2];
    const float* W2  = (const float*)d_in[3];
    const float* bn2 = (const float*)d_in[4];
    const float* W3  = (const float*)d_in[5];
    const float* bn3 = (const float*)d_in[6];
    const float* W4  = (const float*)d_in[7];
    const float* bn4 = (const float*)d_in[8];
    const float* W5  = (const float*)d_in[9];
    const float* bn5 = (const float*)d_in[10];
    const float* Wl1 = (const float*)d_in[11];
    const float* bn6 = (const float*)d_in[12];
    const float* Wl3 = (const float*)d_in[13];
    const float* bl3 = (const float*)d_in[14];
    float* out = (float*)d_out;

    float *XT, *G, *diag, *U, *V, *H, *H5, *pmax, *psum, *pool, *z;
    int* idx;
    cudaGetSymbolAddress((void**)&XT,   g_XT);
    cudaGetSymbolAddress((void**)&G,    g_G);
    cudaGetSymbolAddress((void**)&diag, g_diag);
    cudaGetSymbolAddress((void**)&idx,  g_idx);
    cudaGetSymbolAddress((void**)&U,    g_U);
    cudaGetSymbolAddress((void**)&V,    g_V);
    cudaGetSymbolAddress((void**)&H,    g_H);
    cudaGetSymbolAddress((void**)&H5,   g_H5);
    cudaGetSymbolAddress((void**)&pmax, g_pmax);
    cudaGetSymbolAddress((void**)&psum, g_psum);
    cudaGetSymbolAddress((void**)&pool, g_pool);
    cudaGetSymbolAddress((void**)&z,    g_z);

    // transpose x (B,C,N) -> XT (B,N,C)
    transpose_kernel<<<dim3(NPTS / 32, CIN / 32, BATCH), dim3(32, 8)>>>(x, XT);

    // EdgeConv 1..4, outputs written into slices of H (ld = 1152)
    run_edgeconv(XT,      CIN,  768, W1, bn1, 512, H,       HDIM, G, diag, idx, U, V);
    run_edgeconv(H,       HDIM, 512, W2, bn2, 256, H + 512, HDIM, G, diag, idx, U, V);
    run_edgeconv(H + 512, HDIM, 256, W3, bn3, 128, H + 768, HDIM, G, diag, idx, U, V);
    run_edgeconv(H + 768, HDIM, 128, W4, bn4, 256, H + 896, HDIM, G, diag, idx, U, V);

    // conv5: H (N x 1152) @ W5^T (1152 x 1024) + bn5 + lrelu  -> H5
    launch_gemm2(H, HDIM, (long)NPTS * HDIM, W5, W5, HDIM, 0,
                 H5, H5, 1024, (long)NPTS * 1024, NPTS, 1024, 0, HDIM, bn5, 1024, 0);

    // pooling -> pooled (B x 2048)
    pool1_kernel<<<dim3(PCH, BATCH), 256>>>(H5, pmax, psum);
    pool2_kernel<<<dim3(4, BATCH), 256>>>(pmax, psum, pool);

    // head
    head1_kernel<<<dim3(512, BATCH), 256>>>(pool, Wl1, bn6, z);
    head2_kernel<<<dim3(40, BATCH), 128>>>(z, Wl3, bl3, out);
}

// round 9
// speedup vs baseline: 2.3955x; 2.3955x over previous
#include <cuda_runtime.h>
#include <math_constants.h>

// ---------------------------------------------------------------------------
// Problem constants
// ---------------------------------------------------------------------------
#define BATCH 4
#define NPTS  1024
#define CIN   768
#define KNN   20
#define HDIM  1152    // 512 + 256 + 128 + 256
#define PCH   32      // pooling chunks
#define EPS   1e-5f

// ---------------------------------------------------------------------------
// Scratch (device globals; no allocation allowed)
// ---------------------------------------------------------------------------
__device__ float g_XT [BATCH * NPTS * CIN];     // x transposed: (B, N, C)
__device__ float g_G  [BATCH * NPTS * NPTS];    // gram matrix
__device__ float g_diag[BATCH * NPTS];          // gram diagonal
__device__ int   g_idx[BATCH * NPTS * KNN];     // knn indices
__device__ float g_U  [BATCH * NPTS * 512];     // W_left  @ x
__device__ float g_V  [BATCH * NPTS * 512];     // W_right @ x
__device__ float g_H  [BATCH * NPTS * HDIM];    // concat(x1,x2,x3,x4)
__device__ float g_H5 [BATCH * NPTS * 1024];    // conv5 output
__device__ float g_pmax[BATCH * PCH * 1024];
__device__ float g_psum[BATCH * PCH * 1024];
__device__ float g_pool[BATCH * 2048];
__device__ float g_z   [BATCH * 512];

// ---------------------------------------------------------------------------
// Transpose: x (B, C, N) -> XT (B, N, C)
// ---------------------------------------------------------------------------
__global__ void transpose_kernel(const float* __restrict__ x, float* __restrict__ xt) {
    __shared__ float tile[32][33];
    int b  = blockIdx.z;
    int c0 = blockIdx.y * 32;
    int n0 = blockIdx.x * 32;
    const float* xb  = x  + (long)b * CIN * NPTS;
    float*       xtb = xt + (long)b * NPTS * CIN;
    int tx = threadIdx.x, ty = threadIdx.y;            // 32 x 8
#pragma unroll
    for (int i = 0; i < 32; i += 8)
        tile[ty + i][tx] = xb[(long)(c0 + ty + i) * NPTS + n0 + tx];
    __syncthreads();
#pragma unroll
    for (int i = 0; i < 32; i += 8)
        xtb[(long)(n0 + ty + i) * CIN + c0 + tx] = tile[tx][ty + i];
}

// ---------------------------------------------------------------------------
// Tiled SGEMM with dual-source N split:
//   blocks with nb0 <  N1 compute C1 = A * B1^T
//   blocks with nb0 >= N1 compute C2 = A * B2^T  (column nb0-N1)
// 128x64 tiles, 8x4 per-thread register blocking, double-buffered smem,
// 256 threads, 3 CTAs/SM. Conflict-free smem loads (B at 16B stride).
// Sequential k accumulation -> bit-identical numerics across rounds.
// sym != 0: only blocks with bx <= 2*by+1 computed (Gram symmetry;
//           exactly covers the region mirror_kernel expects).
// Optional epilogue: batchnorm + leaky_relu(0.2).
// Requirements: M % 128 == 0, N % 64 == 0, K % 16 == 0
// ---------------------------------------------------------------------------
#define BM 128
#define BN 64
#define BK 16

__global__ void __launch_bounds__(256, 3)
gemm_nt(const float* __restrict__ A, int lda, long strideA,
        const float* __restrict__ B1, const float* __restrict__ B2,
        int ldb, long strideB,
        float* __restrict__ C1, float* __restrict__ C2,
        int ldc, long strideC,
        int N1, int K,
        const float* __restrict__ bn, int bnN, int sym)
{
    if (sym && (int)blockIdx.x > 2 * (int)blockIdx.y + 1) return;

    __shared__ __align__(16) float As[2][BK][BM];
    __shared__ __align__(16) float Bs[2][BK][BN];

    const int bz = blockIdx.z;
    const int m0 = blockIdx.y * BM;
    const int nb0 = blockIdx.x * BN;

    const float* Bsel;
    float*       Csel;
    int n0;
    if (nb0 < N1) { Bsel = B1; Csel = C1; n0 = nb0; }
    else          { Bsel = B2; Csel = C2; n0 = nb0 - N1; }

    const float* Ab = A    + (long)bz * strideA;
    const float* Bb = Bsel + (long)bz * strideB;
    float*       Cb = Csel + (long)bz * strideC;

    const int tid = threadIdx.x;
    // loader mapping
    const int lr = tid >> 2;            // 0..63
    const int lc = (tid & 3) * 4;       // 0,4,8,12
    // compute mapping: 16x16 thread grid; each thread 8 rows x 4 cols
    const int ty = tid >> 4;            // 0..15
    const int tx = tid & 15;            // 0..15

    float acc[8][4];
#pragma unroll
    for (int i = 0; i < 8; i++)
#pragma unroll
        for (int j = 0; j < 4; j++) acc[i][j] = 0.f;

    const int nTiles = K / BK;
    float4 pa0, pa1, pb0;

    // prefetch tile 0
    pa0 = *reinterpret_cast<const float4*>(&Ab[(long)(m0 + lr)      * lda + lc]);
    pa1 = *reinterpret_cast<const float4*>(&Ab[(long)(m0 + lr + 64) * lda + lc]);
    pb0 = *reinterpret_cast<const float4*>(&Bb[(long)(n0 + lr)      * ldb + lc]);
    As[0][lc + 0][lr] = pa0.x; As[0][lc + 1][lr] = pa0.y;
    As[0][lc + 2][lr] = pa0.z; As[0][lc + 3][lr] = pa0.w;
    As[0][lc + 0][lr + 64] = pa1.x; As[0][lc + 1][lr + 64] = pa1.y;
    As[0][lc + 2][lr + 64] = pa1.z; As[0][lc + 3][lr + 64] = pa1.w;
    Bs[0][lc + 0][lr] = pb0.x; Bs[0][lc + 1][lr] = pb0.y;
    Bs[0][lc + 2][lr] = pb0.z; Bs[0][lc + 3][lr] = pb0.w;
    __syncthreads();

    for (int t = 0; t < nTiles; t++) {
        const int cur = t & 1;
        if (t + 1 < nTiles) {
            const int k0 = (t + 1) * BK;
            pa0 = *reinterpret_cast<const float4*>(&Ab[(long)(m0 + lr)      * lda + k0 + lc]);
            pa1 = *reinterpret_cast<const float4*>(&Ab[(long)(m0 + lr + 64) * lda + k0 + lc]);
            pb0 = *reinterpret_cast<const float4*>(&Bb[(long)(n0 + lr)      * ldb + k0 + lc]);
        }

#pragma unroll
        for (int k = 0; k < BK; k++) {
            float4 a0 = *reinterpret_cast<const float4*>(&As[cur][k][ty * 8]);
            float4 a1 = *reinterpret_cast<const float4*>(&As[cur][k][ty * 8 + 4]);
            float4 b0 = *reinterpret_cast<const float4*>(&Bs[cur][k][tx * 4]);
            float av[8] = {a0.x, a0.y, a0.z, a0.w, a1.x, a1.y, a1.z, a1.w};
            float bv[4] = {b0.x, b0.y, b0.z, b0.w};
#pragma unroll
            for (int i = 0; i < 8; i++)
#pragma unroll
                for (int j = 0; j < 4; j++)
                    acc[i][j] += av[i] * bv[j];
        }

        if (t + 1 < nTiles) {
            const int nxt = 1 - cur;
            As[nxt][lc + 0][lr] = pa0.x; As[nxt][lc + 1][lr] = pa0.y;
            As[nxt][lc + 2][lr] = pa0.z; As[nxt][lc + 3][lr] = pa0.w;
            As[nxt][lc + 0][lr + 64] = pa1.x; As[nxt][lc + 1][lr + 64] = pa1.y;
            As[nxt][lc + 2][lr + 64] = pa1.z; As[nxt][lc + 3][lr + 64] = pa1.w;
            Bs[nxt][lc + 0][lr] = pb0.x; Bs[nxt][lc + 1][lr] = pb0.y;
            Bs[nxt][lc + 2][lr] = pb0.z; Bs[nxt][lc + 3][lr] = pb0.w;
        }
        __syncthreads();
    }

    // epilogue
    const int cm = m0 + ty * 8;
    const int cn = n0 + tx * 4;
    if (bn) {
        float sc[4], sh[4];
#pragma unroll
        for (int j = 0; j < 4; j++) {
            int n = cn + j;
            float g = bn[n], b = bn[bnN + n], m = bn[2 * bnN + n], v = bn[3 * bnN + n];
            sc[j] = g * rsqrtf(v + EPS);
            sh[j] = b - m * sc[j];
        }
#pragma unroll
        for (int i = 0; i < 8; i++) {
#pragma unroll
            for (int j = 0; j < 4; j++) {
                float val = acc[i][j] * sc[j] + sh[j];
                acc[i][j] = val > 0.f ? val : 0.2f * val;
            }
        }
    }
#pragma unroll
    for (int i = 0; i < 8; i++) {
        float4 v0 = make_float4(acc[i][0], acc[i][1], acc[i][2], acc[i][3]);
        *reinterpret_cast<float4*>(&Cb[(long)(cm + i) * ldc + cn]) = v0;
    }
}

// ---------------------------------------------------------------------------
// Gram mirror: fill G[n][m] (m >= 128*((n>>7)+1)) from G[m][n].
// Bit-identical because FMA(a,b,c) == FMA(b,a,c) with same k order.
// ---------------------------------------------------------------------------
__global__ void mirror_kernel(float* __restrict__ G)
{
    int b  = blockIdx.z;
    int m0 = blockIdx.x * 32;   // destination cols
    int n0 = blockIdx.y * 32;   // destination rows
    if (m0 < 128 * ((n0 >> 7) + 1)) return;   // tile already computed

    __shared__ float tile[32][33];
    float* Gb = G + (long)b * NPTS * NPTS;
    int tx = threadIdx.x, ty = threadIdx.y;    // 32 x 8
#pragma unroll
    for (int i = 0; i < 32; i += 8)
        tile[ty + i][tx] = Gb[(long)(m0 + ty + i) * NPTS + n0 + tx];
    __syncthreads();
#pragma unroll
    for (int i = 0; i < 32; i += 8)
        Gb[(long)(n0 + ty + i) * NPTS + m0 + tx] = tile[tx][ty + i];
}

// ---------------------------------------------------------------------------
// Extract Gram diagonal
// ---------------------------------------------------------------------------
__global__ void diag_kernel(const float* __restrict__ G, float* __restrict__ diag)
{
    int t = blockIdx.x * 256 + threadIdx.x;     // over BATCH*NPTS
    int b = t >> 10, m = t & 1023;
    diag[t] = G[((long)b * NPTS + m) * NPTS + m];
}

// ---------------------------------------------------------------------------
// Top-K (K=20): register-resident two-phase selection.
// key[m] = 2*G[n][m] - G[m][m]; descending value, tie -> lower index.
// ---------------------------------------------------------------------------
__global__ void __launch_bounds__(256)
topk_kernel(const float* __restrict__ G, const float* __restrict__ diag,
            int* __restrict__ idx)
{
    const int b = blockIdx.y;
    const int n = blockIdx.x;
    const float* Gb = G + ((long)b * NPTS + n) * NPTS;
    const float* db = diag + b * NPTS;

    const int tid  = threadIdx.x;
    const int lane = tid & 31;
    const int w    = tid >> 5;          // 0..7
    const int base = w * 128;

    float key[4];
#pragma unroll
    for (int q = 0; q < 4; q++) {
        int m = base + lane + 32 * q;
        key[q] = 2.f * Gb[m] - db[m];
    }

    __shared__ float wv[8][KNN];
    __shared__ int   wi[8][KNN];

    // Phase 1: per-warp top-20 (sorted desc, ties by ascending index)
    for (int it = 0; it < KNN; ++it) {
        float bv = key[0];
        int   bi = base + lane;
#pragma unroll
        for (int q = 1; q < 4; q++) {
            if (key[q] > bv) { bv = key[q]; bi = base + lane + 32 * q; }
        }
#pragma unroll
        for (int off = 16; off > 0; off >>= 1) {
            float ov = __shfl_xor_sync(0xffffffffu, bv, off);
            int   oi = __shfl_xor_sync(0xffffffffu, bi, off);
            if (ov > bv || (ov == bv && oi < bi)) { bv = ov; bi = oi; }
        }
        if (lane == 0) { wv[w][it] = bv; wi[w][it] = bi; }
        const int rel   = bi - base;
        const int l_win = rel & 31;
        const int q_win = rel >> 5;
        if (lane == l_win) {
#pragma unroll
            for (int q = 0; q < 4; q++)
                if (q == q_win) key[q] = -CUDART_INF_F;
        }
    }
    __syncthreads();

    // Phase 2: warp 0 merges 8 sorted lists of 20
    if (w == 0) {
        int ptr = 0;
        int* orow = idx + ((long)b * NPTS + n) * KNN;
        for (int it = 0; it < KNN; ++it) {
            float v = (lane < 8) ? wv[lane][ptr] : -CUDART_INF_F;
            int   i = (lane < 8) ? wi[lane][ptr] : 0x7fffffff;
            int   j = lane;
#pragma unroll
            for (int off = 4; off > 0; off >>= 1) {
                float ov = __shfl_xor_sync(0xffffffffu, v, off);
                int   oi = __shfl_xor_sync(0xffffffffu, i, off);
                int   oj = __shfl_xor_sync(0xffffffffu, j, off);
                if (ov > v || (ov == v && oi < i)) { v = ov; i = oi; j = oj; }
            }
            if (lane == 0) orow[it] = i;
            if (lane < 8 && lane == j) ptr++;
        }
    }
}

// ---------------------------------------------------------------------------
// EdgeConv aggregation (float4 across channels):
// out[n][o] = bn_lrelu( max_k U[idx[n,k]][o]  -  U[n][o] + V[n][o] )
// (valid because bn scale > 0 and leaky_relu are monotone increasing)
// ---------------------------------------------------------------------------
__global__ void __launch_bounds__(256)
aggregate_kernel(const float* __restrict__ U, const float* __restrict__ V,
                 const int* __restrict__ idx, const float* __restrict__ bn,
                 float* __restrict__ out, int O, int ldo)
{
    int b = blockIdx.y, n = blockIdx.x;
    __shared__ int nb[KNN];
    int tid = threadIdx.x;
    if (tid < KNN) nb[tid] = idx[((long)b * NPTS + n) * KNN + tid];
    __syncthreads();

    const float* Ub = U + (long)b * NPTS * O;
    const float* un = Ub + (long)n * O;
    const float* vn = V + ((long)b * NPTS + n) * O;
    float*       on = out + ((long)b * NPTS + n) * ldo;

    const int O4 = O >> 2;
    for (int o4 = tid; o4 < O4; o4 += 256) {
        float4 mx = make_float4(-CUDART_INF_F, -CUDART_INF_F, -CUDART_INF_F, -CUDART_INF_F);
#pragma unroll
        for (int k = 0; k < KNN; k++) {
            float4 u = *reinterpret_cast<const float4*>(&Ub[(long)nb[k] * O + o4 * 4]);
            mx.x = fmaxf(mx.x, u.x); mx.y = fmaxf(mx.y, u.y);
            mx.z = fmaxf(mx.z, u.z); mx.w = fmaxf(mx.w, u.w);
        }
        float4 uo = *reinterpret_cast<const float4*>(&un[o4 * 4]);
        float4 vo = *reinterpret_cast<const float4*>(&vn[o4 * 4]);
        float4 gg = *reinterpret_cast<const float4*>(&bn[o4 * 4]);
        float4 be = *reinterpret_cast<const float4*>(&bn[O + o4 * 4]);
        float4 mm = *reinterpret_cast<const float4*>(&bn[2 * O + o4 * 4]);
        float4 vv = *reinterpret_cast<const float4*>(&bn[3 * O + o4 * 4]);
        float y0 = mx.x - uo.x + vo.x, y1 = mx.y - uo.y + vo.y;
        float y2 = mx.z - uo.z + vo.z, y3 = mx.w - uo.w + vo.w;
        float s0 = gg.x * rsqrtf(vv.x + EPS), s1 = gg.y * rsqrtf(vv.y + EPS);
        float s2 = gg.z * rsqrtf(vv.z + EPS), s3 = gg.w * rsqrtf(vv.w + EPS);
        y0 = (y0 - mm.x) * s0 + be.x; y1 = (y1 - mm.y) * s1 + be.y;
        y2 = (y2 - mm.z) * s2 + be.z; y3 = (y3 - mm.w) * s3 + be.w;
        float4 r;
        r.x = y0 > 0.f ? y0 : 0.2f * y0;
        r.y = y1 > 0.f ? y1 : 0.2f * y1;
        r.z = y2 > 0.f ? y2 : 0.2f * y2;
        r.w = y3 > 0.f ? y3 : 0.2f * y3;
        *reinterpret_cast<float4*>(&on[o4 * 4]) = r;
    }
}

// ---------------------------------------------------------------------------
// Pooling (max + mean over N), two-stage
// ---------------------------------------------------------------------------
__global__ void __launch_bounds__(256)
pool1_kernel(const float* __restrict__ H5, float* __restrict__ pmax, float* __restrict__ psum)
{
    int b = blockIdx.y, chunk = blockIdx.x;      // PCH chunks of 32 rows
    int tid = threadIdx.x;
    float mx[4] = {-CUDART_INF_F, -CUDART_INF_F, -CUDART_INF_F, -CUDART_INF_F};
    float sm[4] = {0.f, 0.f, 0.f, 0.f};
    const float* h = H5 + ((long)b * NPTS + chunk * 32) * 1024;
    for (int n = 0; n < 32; n++) {
        const float* row = h + (long)n * 1024;
#pragma unroll
        for (int q = 0; q < 4; q++) {
            float v = row[tid + 256 * q];
            mx[q] = fmaxf(mx[q], v);
            sm[q] += v;
        }
    }
#pragma unroll
    for (int q = 0; q < 4; q++) {
        int o = tid + 256 * q;
        pmax[((long)b * PCH + chunk) * 1024 + o] = mx[q];
        psum[((long)b * PCH + chunk) * 1024 + o] = sm[q];
    }
}

__global__ void __launch_bounds__(256)
pool2_kernel(const float* __restrict__ pmax, const float* __restrict__ psum,
             float* __restrict__ pooled)
{
    int b = blockIdx.y;
    int o = blockIdx.x * 256 + threadIdx.x;      // 0..1023
    float mx = -CUDART_INF_F, sm = 0.f;
    for (int c = 0; c < PCH; c++) {
        mx = fmaxf(mx, pmax[((long)b * PCH + c) * 1024 + o]);
        sm += psum[((long)b * PCH + c) * 1024 + o];
    }
    pooled[b * 2048 + o]        = mx;
    pooled[b * 2048 + 1024 + o] = sm * (1.f / NPTS);
}

// ---------------------------------------------------------------------------
// Head:  z = bn_lrelu(pooled @ Wl1^T);  out = z @ Wl3^T + bl3
// ---------------------------------------------------------------------------
__global__ void __launch_bounds__(256)
head1_kernel(const float* __restrict__ pooled, const float* __restrict__ Wl1,
             const float* __restrict__ bn6, float* __restrict__ z)
{
    int b = blockIdx.y, j = blockIdx.x;          // j < 512
    int tid = threadIdx.x;
    const float* p = pooled + b * 2048;
    const float* w = Wl1 + (long)j * 2048;
    float s = 0.f;
    for (int c = tid; c < 2048; c += 256) s += p[c] * w[c];
    __shared__ float red[256];
    red[tid] = s; __syncthreads();
    for (int st = 128; st > 0; st >>= 1) {
        if (tid < st) red[tid] += red[tid + st];
        __syncthreads();
    }
    if (tid == 0) {
        float y = red[0];
        float g = bn6[j], be = bn6[512 + j], mm = bn6[1024 + j], vv = bn6[1536 + j];
        y = (y - mm) * (g * rsqrtf(vv + EPS)) + be;
        z[b * 512 + j] = y > 0.f ? y : 0.2f * y;
    }
}

__global__ void __launch_bounds__(128)
head2_kernel(const float* __restrict__ z, const float* __restrict__ Wl3,
             const float* __restrict__ bl3, float* __restrict__ out)
{
    int b = blockIdx.y, t = blockIdx.x;          // t < 40
    int tid = threadIdx.x;
    const float* zb = z + b * 512;
    const float* w  = Wl3 + (long)t * 512;
    float s = 0.f;
    for (int c = tid; c < 512; c += 128) s += zb[c] * w[c];
    __shared__ float red[128];
    red[tid] = s; __syncthreads();
    for (int st = 64; st > 0; st >>= 1) {
        if (tid < st) red[tid] += red[tid + st];
        __syncthreads();
    }
    if (tid == 0) out[b * 40 + t] = red[0] + bl3[t];
}

// ---------------------------------------------------------------------------
// Host driver
// ---------------------------------------------------------------------------
static void launch_gemm2(const float* A, int lda, long sA,
                         const float* B1, const float* B2, int ldb, long sB,
                         float* C1, float* C2, int ldc, long sC,
                         int M, int N1, int N2, int K,
                         const float* bn, int bnN, int sym)
{
    dim3 grid((N1 + N2) / BN, M / BM, BATCH);
    gemm_nt<<<grid, 256>>>(A, lda, sA, B1, B2, ldb, sB, C1, C2, ldc, sC, N1, K, bn, bnN, sym);
}

static void run_edgeconv(const float* Xin, int lda, int Kdim,
                         const float* W, const float* bn, int O,
                         float* Hout, int ldo,
                         float* G, float* diag, int* idx, float* U, float* V)
{
    // 1) Gram matrix (lower-triangular block region), mirror
    launch_gemm2(Xin, lda, (long)NPTS * lda, Xin, Xin, lda, (long)NPTS * lda,
                 G, G, NPTS, (long)NPTS * NPTS, NPTS, NPTS, 0, Kdim, nullptr, 0, 1);
    mirror_kernel<<<dim3(NPTS / 32, NPTS / 32, BATCH), dim3(32, 8)>>>(G);
    // 2) fused U/V gemm (4th launch overall for conv1 -> profiled)
    launch_gemm2(Xin, lda, (long)NPTS * lda, W, W + Kdim, 2 * Kdim, 0,
                 U, V, O, (long)NPTS * O, NPTS, O, O, Kdim, nullptr, 0, 0);
    // 3) diag + top-20 per row
    diag_kernel<<<(BATCH * NPTS) / 256, 256>>>(G, diag);
    topk_kernel<<<dim3(NPTS, BATCH), 256>>>(G, diag, idx);
    // 4) gather + max + bn + lrelu
    aggregate_kernel<<<dim3(NPTS, BATCH), 256>>>(U, V, idx, bn, Hout, O, ldo);
}

extern "C" void kernel_launch(void* const* d_in, const int* in_sizes, int n_in,
                              void* d_out, int out_size)
{
    (void)in_sizes; (void)n_in; (void)out_size;
    const float* x   = (const float*)d_in[0];
    const float* W1  = (const float*)d_in[1];
    const float* bn1 = (const float*)d_in[2];
    const float* W2  = (const float*)d_in[3];
    const float* bn2 = (const float*)d_in[4];
    const float* W3  = (const float*)d_in[5];
    const float* bn3 = (const float*)d_in[6];
    const float* W4  = (const float*)d_in[7];
    const float* bn4 = (const float*)d_in[8];
    const float* W5  = (const float*)d_in[9];
    const float* bn5 = (const float*)d_in[10];
    const float* Wl1 = (const float*)d_in[11];
    const float* bn6 = (const float*)d_in[12];
    const float* Wl3 = (const float*)d_in[13];
    const float* bl3 = (const float*)d_in[14];
    float* out = (float*)d_out;

    float *XT, *G, *diag, *U, *V, *H, *H5, *pmax, *psum, *pool, *z;
    int* idx;
    cudaGetSymbolAddress((void**)&XT,   g_XT);
    cudaGetSymbolAddress((void**)&G,    g_G);
    cudaGetSymbolAddress((void**)&diag, g_diag);
    cudaGetSymbolAddress((void**)&idx,  g_idx);
    cudaGetSymbolAddress((void**)&U,    g_U);
    cudaGetSymbolAddress((void**)&V,    g_V);
    cudaGetSymbolAddress((void**)&H,    g_H);
    cudaGetSymbolAddress((void**)&H5,   g_H5);
    cudaGetSymbolAddress((void**)&pmax, g_pmax);
    cudaGetSymbolAddress((void**)&psum, g_psum);
    cudaGetSymbolAddress((void**)&pool, g_pool);
    cudaGetSymbolAddress((void**)&z,    g_z);

    // transpose x (B,C,N) -> XT (B,N,C)
    transpose_kernel<<<dim3(NPTS / 32, CIN / 32, BATCH), dim3(32, 8)>>>(x, XT);

    // EdgeConv 1..4, outputs written into slices of H (ld = 1152)
    run_edgeconv(XT,      CIN,  768, W1, bn1, 512, H,       HDIM, G, diag, idx, U, V);
    run_edgeconv(H,       HDIM, 512, W2, bn2, 256, H + 512, HDIM, G, diag, idx, U, V);
    run_edgeconv(H + 512, HDIM, 256, W3, bn3, 128, H + 768, HDIM, G, diag, idx, U, V);
    run_edgeconv(H + 768, HDIM, 128, W4, bn4, 256, H + 896, HDIM, G, diag, idx, U, V);

    // conv5: H (N x 1152) @ W5^T (1152 x 1024) + bn5 + lrelu  -> H5
    launch_gemm2(H, HDIM, (long)NPTS * HDIM, W5, W5, HDIM, 0,
                 H5, H5, 1024, (long)NPTS * 1024, NPTS, 1024, 0, HDIM, bn5, 1024, 0);

    // pooling -> pooled (B x 2048)
    pool1_kernel<<<dim3(PCH, BATCH), 256>>>(H5, pmax, psum);
    pool2_kernel<<<dim3(4, BATCH), 256>>>(pmax, psum, pool);

    // head
    head1_kernel<<<dim3(512, BATCH), 256>>>(pool, Wl1, bn6, z);
    head2_kernel<<<dim3(40, BATCH), 128>>>(z, Wl3, bl3, out);
}